// round 4
// baseline (speedup 1.0000x reference)
#include <cuda_runtime.h>
#include <cstdint>

// ---------------------------------------------------------------------------
// Problem constants
// ---------------------------------------------------------------------------
#define B_  32
#define D_  3
#define T_  16384
#define S_  128
#define L_  16
#define H_  512
#define C_  10
#define TP  16369          // T - L + 1 valid positions
#define SHN 48             // D*L  (= K, divisible by 8: 6 k-steps)

#define NT      128        // positions per block tile (GEMM N-tile)
#define NTILES  (B_ * (T_ / NT))   // 4096
#define THR     256
#define GRID    296        // 2 blocks / SM
#define ASTRIDE 52         // A smem row stride (floats) — conflict-free
#define XT_W    (NT + L_)  // 144 floats per x row in smem

#define INF_F __int_as_float(0x7F800000)

// ---------------------------------------------------------------------------
__device__ __forceinline__ float tf32r(float f) {
    uint32_t u;
    asm("cvt.rna.tf32.f32 %0, %1;" : "=r"(u) : "f"(f));
    return __uint_as_float(u);
}

// D += A(16x8,row) * B(8x8,col)   tf32 -> f32
__device__ __forceinline__ void mma8(float* d, uint32_t a0, uint32_t a1,
                                     uint32_t a2, uint32_t a3,
                                     uint32_t b0, uint32_t b1) {
    asm volatile(
        "mma.sync.aligned.m16n8k8.row.col.f32.tf32.tf32.f32 "
        "{%0,%1,%2,%3}, {%4,%5,%6,%7}, {%8,%9}, {%0,%1,%2,%3};"
        : "+f"(d[0]), "+f"(d[1]), "+f"(d[2]), "+f"(d[3])
        : "r"(a0), "r"(a1), "r"(a2), "r"(a3), "r"(b0), "r"(b1));
}

// ---------------------------------------------------------------------------
// Kernel 0: init distances to +inf
// ---------------------------------------------------------------------------
__global__ void init_kernel(float* out_dist) {
    int i = blockIdx.x * blockDim.x + threadIdx.x;
    if (i < B_ * S_) reinterpret_cast<int*>(out_dist)[i] = 0x7F800000;
}

// ---------------------------------------------------------------------------
// Kernel 1: persistent tf32-MMA shapelet distance
//   A (smem, [128 x 48] stride 52) = -2 * tf32(shapelet)
//   B = sliding windows, read in-place from tf32-rounded x tile
//   D = -2*corr ; dist = min_n (D + wsq[n]) + ssq[m]
// ---------------------------------------------------------------------------
__global__ __launch_bounds__(THR, 2) void dist_kernel(
    const float* __restrict__ x,
    const float* __restrict__ shg,
    float* __restrict__ out_dist)
{
    __shared__ float sA[S_ * ASTRIDE];      // 26624 B
    __shared__ float xs[D_ * XT_W];         // raw, then tf32-rounded in place
    __shared__ float swsq[NT];
    __shared__ float sssq[S_];
    __shared__ int   sdmin[S_];

    const int tid  = threadIdx.x;
    const int wid  = tid >> 5;
    const int lane = tid & 31;
    const int q    = lane >> 2;      // groupID
    const int r    = lane & 3;       // threadID_in_group

    // --- one-time: load shapelets as -2*tf32(a); exact fp32 squared norms ---
    for (int idx = tid; idx < S_ * SHN; idx += THR) {
        const int m = idx / SHN, k = idx - m * SHN;
        sA[m * ASTRIDE + k] = tf32r(shg[idx]) * -2.0f;
    }
    if (tid < S_) {
        const float* srow = shg + tid * SHN;
        float ssq = 0.f;
        #pragma unroll
        for (int k = 0; k < SHN; ++k) ssq = fmaf(srow[k], srow[k], ssq);
        sssq[tid] = ssq;
    }
    __syncthreads();

    const int mbase = (wid & 3) * 32;       // warp's 32 M-rows
    const int nbase = (wid >> 2) * 64;      // warp's 64 N-cols

    for (int tile = blockIdx.x; tile < NTILES; tile += GRID) {
        const int b     = tile >> 7;                     // 128 tiles / batch
        const int tbase = (tile & 127) * NT;
        const float* xb = x + (size_t)b * D_ * T_;

        // reset per-tile min + load raw x tile (zero-pad past T)
        if (tid < S_) sdmin[tid] = 0x7F800000;
        #pragma unroll
        for (int i = tid; i < D_ * XT_W; i += THR) {
            const int d = i / XT_W, j = i - d * XT_W;
            const int g = tbase + j;
            xs[i] = (g < T_) ? xb[d * T_ + g] : 0.f;
        }
        __syncthreads();

        // window squares from RAW x (exact); poison invalid tail positions
        if (tid < NT) {
            float wacc = 0.f;
            #pragma unroll
            for (int d = 0; d < D_; ++d) {
                #pragma unroll
                for (int l = 0; l < L_; ++l) {
                    const float v = xs[d * XT_W + tid + l];
                    wacc = fmaf(v, v, wacc);
                }
            }
            swsq[tid] = (tbase + tid < TP) ? wacc : INF_F;
        }
        __syncthreads();

        // round x tile to tf32 in place
        #pragma unroll
        for (int i = tid; i < D_ * XT_W; i += THR) xs[i] = tf32r(xs[i]);
        __syncthreads();

        // ===== MMA: acc[mt][nt][4], warp tile 32M x 64N, K=48 =====
        float acc[2][8][4];
        #pragma unroll
        for (int mt = 0; mt < 2; ++mt)
            #pragma unroll
            for (int nt = 0; nt < 8; ++nt)
                #pragma unroll
                for (int e = 0; e < 4; ++e) acc[mt][nt][e] = 0.f;

        const uint32_t* sAu = reinterpret_cast<const uint32_t*>(sA);
        const uint32_t* xsu = reinterpret_cast<const uint32_t*>(xs);

        #pragma unroll
        for (int ks = 0; ks < 6; ++ks) {
            const int d  = ks >> 1;
            const int l0 = (ks & 1) * 8;
            const int kc = ks * 8 + r;

            uint32_t a[2][4];
            #pragma unroll
            for (int mt = 0; mt < 2; ++mt) {
                const int rowb = mbase + mt * 16;
                a[mt][0] = sAu[(rowb + q    ) * ASTRIDE + kc    ];
                a[mt][1] = sAu[(rowb + q + 8) * ASTRIDE + kc    ];
                a[mt][2] = sAu[(rowb + q    ) * ASTRIDE + kc + 4];
                a[mt][3] = sAu[(rowb + q + 8) * ASTRIDE + kc + 4];
            }
            const uint32_t* xr = xsu + d * XT_W + l0 + r;
            #pragma unroll
            for (int nt = 0; nt < 8; ++nt) {
                const int n = nbase + nt * 8 + q;
                const uint32_t b0 = xr[n];
                const uint32_t b1 = xr[n + 4];
                mma8(acc[0][nt], a[0][0], a[0][1], a[0][2], a[0][3], b0, b1);
                mma8(acc[1][nt], a[1][0], a[1][1], a[1][2], a[1][3], b0, b1);
            }
        }

        // ===== epilogue: dist = min_n(acc + wsq[n]) + ssq[m] =====
        float wq[8][2];
        #pragma unroll
        for (int nt = 0; nt < 8; ++nt) {
            wq[nt][0] = swsq[nbase + nt * 8 + r * 2    ];
            wq[nt][1] = swsq[nbase + nt * 8 + r * 2 + 1];
        }
        // rows handled by this thread: mbase + mt*16 + h*8 + q
        float rmin[2][2];
        #pragma unroll
        for (int mt = 0; mt < 2; ++mt)
            #pragma unroll
            for (int h = 0; h < 2; ++h) {
                float m = INF_F;
                #pragma unroll
                for (int nt = 0; nt < 8; ++nt) {
                    m = fminf(m, acc[mt][nt][h * 2    ] + wq[nt][0]);
                    m = fminf(m, acc[mt][nt][h * 2 + 1] + wq[nt][1]);
                }
                rmin[mt][h] = m;
            }
        // quad reduce (lanes sharing q hold the same rows)
        #pragma unroll
        for (int mt = 0; mt < 2; ++mt)
            #pragma unroll
            for (int h = 0; h < 2; ++h) {
                float v = rmin[mt][h];
                v = fminf(v, __shfl_xor_sync(0xffffffffu, v, 1));
                v = fminf(v, __shfl_xor_sync(0xffffffffu, v, 2));
                rmin[mt][h] = v;
            }
        if (r == 0) {
            #pragma unroll
            for (int mt = 0; mt < 2; ++mt)
                #pragma unroll
                for (int h = 0; h < 2; ++h) {
                    const int row = mbase + mt * 16 + h * 8 + q;
                    const float v = rmin[mt][h] + sssq[row];
                    atomicMin(&sdmin[row], __float_as_int(v));
                }
        }
        __syncthreads();

        if (tid < S_)
            atomicMin(reinterpret_cast<int*>(out_dist) + b * S_ + tid, sdmin[tid]);
        __syncthreads();
    }
}

// ---------------------------------------------------------------------------
// Kernel 2: fused MLP
// ---------------------------------------------------------------------------
__global__ void mlp_kernel(const float* __restrict__ dist,
                           const float* __restrict__ W1,
                           const float* __restrict__ b1,
                           const float* __restrict__ W2,
                           const float* __restrict__ b2,
                           float* __restrict__ out_cls)
{
    __shared__ float ds[S_];
    __shared__ float hs[H_];
    const int b = blockIdx.x;
    const int tid = threadIdx.x;   // 512

    if (tid < S_) ds[tid] = dist[b * S_ + tid];
    __syncthreads();

    {
        float acc = b1[tid];
        const float* w = W1 + tid * S_;
        #pragma unroll 8
        for (int s2 = 0; s2 < S_; ++s2) acc = fmaf(ds[s2], w[s2], acc);
        hs[tid] = fmaxf(acc, 0.f);
    }
    __syncthreads();

    const int warp = tid >> 5, lane = tid & 31;
    if (warp < C_) {
        const float* w = W2 + warp * H_;
        float acc = 0.f;
        #pragma unroll
        for (int j = lane; j < H_; j += 32) acc = fmaf(hs[j], w[j], acc);
        #pragma unroll
        for (int off = 16; off > 0; off >>= 1)
            acc += __shfl_down_sync(0xffffffffu, acc, off);
        if (lane == 0) out_cls[b * C_ + warp] = acc + b2[warp];
    }
}

// ---------------------------------------------------------------------------
extern "C" void kernel_launch(void* const* d_in, const int* in_sizes, int n_in,
                              void* d_out, int out_size)
{
    const float* x  = (const float*)d_in[0];
    const float* sh = (const float*)d_in[1];
    const float* W1 = (const float*)d_in[2];
    const float* b1 = (const float*)d_in[3];
    const float* W2 = (const float*)d_in[4];
    const float* b2 = (const float*)d_in[5];

    float* out_dist = (float*)d_out;
    float* out_cls  = (float*)d_out + B_ * S_;

    init_kernel<<<(B_ * S_ + 255) / 256, 256>>>(out_dist);
    dist_kernel<<<GRID, THR>>>(x, sh, out_dist);
    mlp_kernel<<<B_, H_>>>(out_dist, W1, b1, W2, b2, out_cls);
}

// round 5
// speedup vs baseline: 1.0078x; 1.0078x over previous
#include <cuda_runtime.h>
#include <cstdint>

// ---------------------------------------------------------------------------
// Problem constants
// ---------------------------------------------------------------------------
#define B_  32
#define D_  3
#define T_  16384
#define S_  128
#define L_  16
#define H_  512
#define C_  10
#define TP  16369          // T - L + 1 valid positions
#define SHN 48             // D*L  (= K, divisible by 8: 6 k-steps)

#define NT      128        // positions per block tile (GEMM N-tile)
#define NTILES  (B_ * (T_ / NT))   // 4096
#define THR     256
#define GRID    296        // 2 blocks / SM
#define ASTRIDE 52         // A smem row stride (floats) — conflict-free
#define XT_W    (NT + L_)  // 144 floats per x row in smem

#define INF_F __int_as_float(0x7F800000)

// ---------------------------------------------------------------------------
__device__ __forceinline__ float tf32r(float f) {
    uint32_t u;
    asm("cvt.rna.tf32.f32 %0, %1;" : "=r"(u) : "f"(f));
    return __uint_as_float(u);
}

// D += A(16x8,row) * B(8x8,col)   tf32 -> f32
__device__ __forceinline__ void mma8(float* d, uint32_t a0, uint32_t a1,
                                     uint32_t a2, uint32_t a3,
                                     uint32_t b0, uint32_t b1) {
    asm volatile(
        "mma.sync.aligned.m16n8k8.row.col.f32.tf32.tf32.f32 "
        "{%0,%1,%2,%3}, {%4,%5,%6,%7}, {%8,%9}, {%0,%1,%2,%3};"
        : "+f"(d[0]), "+f"(d[1]), "+f"(d[2]), "+f"(d[3])
        : "r"(a0), "r"(a1), "r"(a2), "r"(a3), "r"(b0), "r"(b1));
}

// ---------------------------------------------------------------------------
// Kernel 0: init distances to +inf
// ---------------------------------------------------------------------------
__global__ void init_kernel(float* out_dist) {
    int i = blockIdx.x * blockDim.x + threadIdx.x;
    if (i < B_ * S_) reinterpret_cast<int*>(out_dist)[i] = 0x7F800000;
}

// ---------------------------------------------------------------------------
// Kernel 1: persistent tf32-MMA shapelet distance
//   A (smem, [128 x 48] stride 52) = -2 * tf32(shapelet)
//   B = sliding windows, read in-place from tf32-rounded x tile
//   D = -2*corr ; dist = min_n (D + wsq[n]) + ssq[m]
// ---------------------------------------------------------------------------
__global__ __launch_bounds__(THR, 2) void dist_kernel(
    const float* __restrict__ x,
    const float* __restrict__ shg,
    float* __restrict__ out_dist)
{
    __shared__ float sA[S_ * ASTRIDE];      // 26624 B
    __shared__ float xs[D_ * XT_W];         // raw, then tf32-rounded in place
    __shared__ float swsq[NT];
    __shared__ float sssq[S_];
    __shared__ int   sdmin[S_];

    const int tid  = threadIdx.x;
    const int wid  = tid >> 5;
    const int lane = tid & 31;
    const int q    = lane >> 2;      // groupID
    const int r    = lane & 3;       // threadID_in_group

    // --- one-time: load shapelets as -2*tf32(a); exact fp32 squared norms ---
    for (int idx = tid; idx < S_ * SHN; idx += THR) {
        const int m = idx / SHN, k = idx - m * SHN;
        sA[m * ASTRIDE + k] = tf32r(shg[idx]) * -2.0f;
    }
    if (tid < S_) {
        const float* srow = shg + tid * SHN;
        float ssq = 0.f;
        #pragma unroll
        for (int k = 0; k < SHN; ++k) ssq = fmaf(srow[k], srow[k], ssq);
        sssq[tid] = ssq;
    }
    __syncthreads();

    const int mbase = (wid & 3) * 32;       // warp's 32 M-rows
    const int nbase = (wid >> 2) * 64;      // warp's 64 N-cols

    for (int tile = blockIdx.x; tile < NTILES; tile += GRID) {
        const int b     = tile >> 7;                     // 128 tiles / batch
        const int tbase = (tile & 127) * NT;
        const float* xb = x + (size_t)b * D_ * T_;

        // reset per-tile min + load raw x tile (zero-pad past T)
        if (tid < S_) sdmin[tid] = 0x7F800000;
        #pragma unroll
        for (int i = tid; i < D_ * XT_W; i += THR) {
            const int d = i / XT_W, j = i - d * XT_W;
            const int g = tbase + j;
            xs[i] = (g < T_) ? xb[d * T_ + g] : 0.f;
        }
        __syncthreads();

        // window squares from RAW x (exact); poison invalid tail positions
        if (tid < NT) {
            float wacc = 0.f;
            #pragma unroll
            for (int d = 0; d < D_; ++d) {
                #pragma unroll
                for (int l = 0; l < L_; ++l) {
                    const float v = xs[d * XT_W + tid + l];
                    wacc = fmaf(v, v, wacc);
                }
            }
            swsq[tid] = (tbase + tid < TP) ? wacc : INF_F;
        }
        __syncthreads();

        // round x tile to tf32 in place
        #pragma unroll
        for (int i = tid; i < D_ * XT_W; i += THR) xs[i] = tf32r(xs[i]);
        __syncthreads();

        // ===== MMA: acc[mt][nt][4], warp tile 32M x 64N, K=48 =====
        float acc[2][8][4];
        #pragma unroll
        for (int mt = 0; mt < 2; ++mt)
            #pragma unroll
            for (int nt = 0; nt < 8; ++nt)
                #pragma unroll
                for (int e = 0; e < 4; ++e) acc[mt][nt][e] = 0.f;

        const uint32_t* sAu = reinterpret_cast<const uint32_t*>(sA);
        const uint32_t* xsu = reinterpret_cast<const uint32_t*>(xs);

        #pragma unroll
        for (int ks = 0; ks < 6; ++ks) {
            const int d  = ks >> 1;
            const int l0 = (ks & 1) * 8;
            const int kc = ks * 8 + r;

            uint32_t a[2][4];
            #pragma unroll
            for (int mt = 0; mt < 2; ++mt) {
                const int rowb = mbase + mt * 16;
                a[mt][0] = sAu[(rowb + q    ) * ASTRIDE + kc    ];
                a[mt][1] = sAu[(rowb + q + 8) * ASTRIDE + kc    ];
                a[mt][2] = sAu[(rowb + q    ) * ASTRIDE + kc + 4];
                a[mt][3] = sAu[(rowb + q + 8) * ASTRIDE + kc + 4];
            }
            const uint32_t* xr = xsu + d * XT_W + l0 + r;
            #pragma unroll
            for (int nt = 0; nt < 8; ++nt) {
                const int n = nbase + nt * 8 + q;
                const uint32_t b0 = xr[n];
                const uint32_t b1 = xr[n + 4];
                mma8(acc[0][nt], a[0][0], a[0][1], a[0][2], a[0][3], b0, b1);
                mma8(acc[1][nt], a[1][0], a[1][1], a[1][2], a[1][3], b0, b1);
            }
        }

        // ===== epilogue: dist = min_n(acc + wsq[n]) + ssq[m] =====
        float wq[8][2];
        #pragma unroll
        for (int nt = 0; nt < 8; ++nt) {
            wq[nt][0] = swsq[nbase + nt * 8 + r * 2    ];
            wq[nt][1] = swsq[nbase + nt * 8 + r * 2 + 1];
        }
        // rows handled by this thread: mbase + mt*16 + h*8 + q
        float rmin[2][2];
        #pragma unroll
        for (int mt = 0; mt < 2; ++mt)
            #pragma unroll
            for (int h = 0; h < 2; ++h) {
                float m = INF_F;
                #pragma unroll
                for (int nt = 0; nt < 8; ++nt) {
                    m = fminf(m, acc[mt][nt][h * 2    ] + wq[nt][0]);
                    m = fminf(m, acc[mt][nt][h * 2 + 1] + wq[nt][1]);
                }
                rmin[mt][h] = m;
            }
        // quad reduce (lanes sharing q hold the same rows)
        #pragma unroll
        for (int mt = 0; mt < 2; ++mt)
            #pragma unroll
            for (int h = 0; h < 2; ++h) {
                float v = rmin[mt][h];
                v = fminf(v, __shfl_xor_sync(0xffffffffu, v, 1));
                v = fminf(v, __shfl_xor_sync(0xffffffffu, v, 2));
                rmin[mt][h] = v;
            }
        if (r == 0) {
            #pragma unroll
            for (int mt = 0; mt < 2; ++mt)
                #pragma unroll
                for (int h = 0; h < 2; ++h) {
                    const int row = mbase + mt * 16 + h * 8 + q;
                    const float v = rmin[mt][h] + sssq[row];
                    atomicMin(&sdmin[row], __float_as_int(v));
                }
        }
        __syncthreads();

        if (tid < S_)
            atomicMin(reinterpret_cast<int*>(out_dist) + b * S_ + tid, sdmin[tid]);
        __syncthreads();
    }
}

// ---------------------------------------------------------------------------
// Kernel 2: fused MLP
// ---------------------------------------------------------------------------
__global__ void mlp_kernel(const float* __restrict__ dist,
                           const float* __restrict__ W1,
                           const float* __restrict__ b1,
                           const float* __restrict__ W2,
                           const float* __restrict__ b2,
                           float* __restrict__ out_cls)
{
    __shared__ float ds[S_];
    __shared__ float hs[H_];
    const int b = blockIdx.x;
    const int tid = threadIdx.x;   // 512

    if (tid < S_) ds[tid] = dist[b * S_ + tid];
    __syncthreads();

    {
        float acc = b1[tid];
        const float* w = W1 + tid * S_;
        #pragma unroll 8
        for (int s2 = 0; s2 < S_; ++s2) acc = fmaf(ds[s2], w[s2], acc);
        hs[tid] = fmaxf(acc, 0.f);
    }
    __syncthreads();

    const int warp = tid >> 5, lane = tid & 31;
    if (warp < C_) {
        const float* w = W2 + warp * H_;
        float acc = 0.f;
        #pragma unroll
        for (int j = lane; j < H_; j += 32) acc = fmaf(hs[j], w[j], acc);
        #pragma unroll
        for (int off = 16; off > 0; off >>= 1)
            acc += __shfl_down_sync(0xffffffffu, acc, off);
        if (lane == 0) out_cls[b * C_ + warp] = acc + b2[warp];
    }
}

// ---------------------------------------------------------------------------
extern "C" void kernel_launch(void* const* d_in, const int* in_sizes, int n_in,
                              void* d_out, int out_size)
{
    const float* x  = (const float*)d_in[0];
    const float* sh = (const float*)d_in[1];
    const float* W1 = (const float*)d_in[2];
    const float* b1 = (const float*)d_in[3];
    const float* W2 = (const float*)d_in[4];
    const float* b2 = (const float*)d_in[5];

    float* out_dist = (float*)d_out;
    float* out_cls  = (float*)d_out + B_ * S_;

    init_kernel<<<(B_ * S_ + 255) / 256, 256>>>(out_dist);
    dist_kernel<<<GRID, THR>>>(x, sh, out_dist);
    mlp_kernel<<<B_, H_>>>(out_dist, W1, b1, W2, b2, out_cls);
}

// round 6
// speedup vs baseline: 1.3021x; 1.2920x over previous
#include <cuda_runtime.h>
#include <cuda_fp16.h>
#include <cstdint>

// ---------------------------------------------------------------------------
// Problem constants
// ---------------------------------------------------------------------------
#define B_  32
#define D_  3
#define T_  16384
#define S_  128
#define L_  16
#define H_  512
#define C_  10
#define TP  16369          // T - L + 1 valid positions
#define SHN 48             // D*L = K (3 k-steps of 16)

#define NT      128        // positions per block tile (GEMM N-tile)
#define NTILES  (B_ * (T_ / NT))   // 4096
#define THR     256
#define GRID    296        // 2 blocks / SM
#define XT_W    (NT + L_)  // 144 elements per x row in tile

#define INF_F __int_as_float(0x7F800000)

// ---------------------------------------------------------------------------
// D(16x8) += A(16x16,row) * B(16x8,col)   f16 x f16 -> f32
__device__ __forceinline__ void mma16(float* d, uint32_t a0, uint32_t a1,
                                      uint32_t a2, uint32_t a3,
                                      uint32_t b0, uint32_t b1) {
    asm volatile(
        "mma.sync.aligned.m16n8k16.row.col.f32.f16.f16.f32 "
        "{%0,%1,%2,%3}, {%4,%5,%6,%7}, {%8,%9}, {%0,%1,%2,%3};"
        : "+f"(d[0]), "+f"(d[1]), "+f"(d[2]), "+f"(d[3])
        : "r"(a0), "r"(a1), "r"(a2), "r"(a3), "r"(b0), "r"(b1));
}

__device__ __forceinline__ uint32_t packh2(float lo, float hi) {
    __half2 h = __floats2half2_rn(lo, hi);
    return *reinterpret_cast<uint32_t*>(&h);
}

// ---------------------------------------------------------------------------
// Kernel 1: persistent fp16-MMA shapelet distance
//   A (registers) = -2 * f16(shapelet)   [tile-invariant, hoisted]
//   B = sliding windows read from parity-duplicated fp16 x tile in smem
//   D = -2*corr ; dist = min_n (D + wsq[n]) + ssq[m]
// ---------------------------------------------------------------------------
__global__ __launch_bounds__(THR, 2) void dist_kernel(
    const float* __restrict__ x,
    const float* __restrict__ shg,
    float* __restrict__ out_dist)
{
    __shared__ float  xs[D_ * XT_W];        // raw fp32 (for exact wsq)
    __shared__ __half hA[D_ * XT_W];        // hA[i]  = f16(x[i])   (even-pair copy)
    __shared__ __half hB[D_ * XT_W];        // hB[i]  = f16(x[i+1]) (odd-pair copy)
    __shared__ float  swsq[NT];
    __shared__ float  sssq[S_];
    __shared__ int    sdmin[S_];

    const int tid  = threadIdx.x;
    const int wid  = tid >> 5;
    const int lane = tid & 31;
    const int q    = lane >> 2;      // groupID
    const int r    = lane & 3;       // threadID_in_group

    const int mbase = (wid & 3) * 32;       // warp's 32 M-rows
    const int nbase = (wid >> 2) * 64;      // warp's 64 N-cols

    // --- one-time: exact fp32 shapelet squared norms; A fragments -> regs ---
    if (tid < S_) {
        const float* srow = shg + tid * SHN;
        float ssq = 0.f;
        #pragma unroll
        for (int k = 0; k < SHN; ++k) ssq = fmaf(srow[k], srow[k], ssq);
        sssq[tid] = ssq;
        sdmin[tid] = 0x7F800000;
    }

    // A fragments: afr[ks][mt][4]; k = ks*16 + kk
    uint32_t afr[3][2][4];
    #pragma unroll
    for (int ks = 0; ks < 3; ++ks) {
        #pragma unroll
        for (int mt = 0; mt < 2; ++mt) {
            const int r0 = mbase + mt * 16 + q;       // row for a0/a2
            const int r1 = r0 + 8;                    // row for a1/a3
            const int k0 = ks * 16 + 2 * r;
            const float* p0 = shg + r0 * SHN + k0;
            const float* p1 = shg + r1 * SHN + k0;
            afr[ks][mt][0] = packh2(-2.f * p0[0], -2.f * p0[1]);
            afr[ks][mt][1] = packh2(-2.f * p1[0], -2.f * p1[1]);
            afr[ks][mt][2] = packh2(-2.f * p0[8], -2.f * p0[9]);
            afr[ks][mt][3] = packh2(-2.f * p1[8], -2.f * p1[9]);
        }
    }
    __syncthreads();

    const uint32_t* hA32 = reinterpret_cast<const uint32_t*>(hA);
    const uint32_t* hB32 = reinterpret_cast<const uint32_t*>(hB);
    // parity select: q even -> aligned copy, q odd -> shifted copy
    const uint32_t* hw = (q & 1) ? hB32 : hA32;
    const int lane_off = q + 2 * r - (q & 1);   // within-row half-index offset

    for (int tile = blockIdx.x; tile < NTILES; tile += GRID) {
        const int b     = tile >> 7;                  // 128 tiles / batch
        const int tbase = (tile & 127) * NT;
        const float* xb = x + (size_t)b * D_ * T_;

        // ---- phase 1: load x tile (fp32 + two fp16 copies) ----
        {
            const int idx4 = tid;                     // 108 float4 total
            if (idx4 < (D_ * XT_W) / 4) {
                const int d = idx4 / (XT_W / 4);
                const int j = (idx4 % (XT_W / 4)) * 4;
                const int g = tbase + j;
                float4 v;
                if (g + 3 < T_) {
                    v = *reinterpret_cast<const float4*>(xb + d * T_ + g);
                } else {
                    v.x = (g     < T_) ? xb[d*T_ + g]     : 0.f;
                    v.y = (g + 1 < T_) ? xb[d*T_ + g + 1] : 0.f;
                    v.z = (g + 2 < T_) ? xb[d*T_ + g + 2] : 0.f;
                    v.w = (g + 3 < T_) ? xb[d*T_ + g + 3] : 0.f;
                }
                *reinterpret_cast<float4*>(&xs[d * XT_W + j]) = v;
                const int hi = d * XT_W + j;
                // aligned copy: hA[i] = f16(x[i])
                *reinterpret_cast<uint32_t*>(&hA[hi])     = packh2(v.x, v.y);
                *reinterpret_cast<uint32_t*>(&hA[hi + 2]) = packh2(v.z, v.w);
                // shifted copy: hB[i] = f16(x[i+1])
                if (j > 0) hB[hi - 1] = __float2half(v.x);
                hB[hi    ] = __float2half(v.y);
                hB[hi + 1] = __float2half(v.z);
                hB[hi + 2] = __float2half(v.w);
            }
        }
        __syncthreads();

        // ---- phase 2: wsq (warps 0-3) from raw fp32, poison invalid tail ----
        if (tid < NT) {
            float w0 = 0.f, w1 = 0.f, w2 = 0.f;
            #pragma unroll
            for (int l = 0; l < L_; ++l) {
                const float v0 = xs[0 * XT_W + tid + l];
                const float v1 = xs[1 * XT_W + tid + l];
                const float v2 = xs[2 * XT_W + tid + l];
                w0 = fmaf(v0, v0, w0);
                w1 = fmaf(v1, v1, w1);
                w2 = fmaf(v2, v2, w2);
            }
            swsq[tid] = (tbase + tid < TP) ? (w0 + w1 + w2) : INF_F;
        }

        // ---- phase 3: MMA, warp tile 32M x 64N, K=48 (3 k-steps) ----
        float acc[2][8][4];
        #pragma unroll
        for (int mt = 0; mt < 2; ++mt)
            #pragma unroll
            for (int nt = 0; nt < 8; ++nt)
                #pragma unroll
                for (int e = 0; e < 4; ++e) acc[mt][nt][e] = 0.f;

        #pragma unroll
        for (int ks = 0; ks < 3; ++ks) {
            // word index of b0 for nt=0 (halves -> 32-bit words)
            const int base = (ks * XT_W + nbase + lane_off) >> 1;
            #pragma unroll
            for (int nt = 0; nt < 8; ++nt) {
                const uint32_t b0 = hw[base + nt * 4];
                const uint32_t b1 = hw[base + nt * 4 + 4];
                mma16(acc[0][nt], afr[ks][0][0], afr[ks][0][1],
                                  afr[ks][0][2], afr[ks][0][3], b0, b1);
                mma16(acc[1][nt], afr[ks][1][0], afr[ks][1][1],
                                  afr[ks][1][2], afr[ks][1][3], b0, b1);
            }
        }
        __syncthreads();   // swsq ready

        // ---- phase 4: dist = min_n(acc + wsq[n]); smem atomic min ----
        float wq[8][2];
        #pragma unroll
        for (int nt = 0; nt < 8; ++nt) {
            wq[nt][0] = swsq[nbase + nt * 8 + r * 2    ];
            wq[nt][1] = swsq[nbase + nt * 8 + r * 2 + 1];
        }
        float rmin[2][2];
        #pragma unroll
        for (int mt = 0; mt < 2; ++mt)
            #pragma unroll
            for (int h = 0; h < 2; ++h) {
                float m = INF_F;
                #pragma unroll
                for (int nt = 0; nt < 8; ++nt) {
                    m = fminf(m, acc[mt][nt][h * 2    ] + wq[nt][0]);
                    m = fminf(m, acc[mt][nt][h * 2 + 1] + wq[nt][1]);
                }
                rmin[mt][h] = m;
            }
        #pragma unroll
        for (int mt = 0; mt < 2; ++mt)
            #pragma unroll
            for (int h = 0; h < 2; ++h) {
                float v = rmin[mt][h];
                v = fminf(v, __shfl_xor_sync(0xffffffffu, v, 1));
                v = fminf(v, __shfl_xor_sync(0xffffffffu, v, 2));
                rmin[mt][h] = v;
            }
        if (r == 0) {
            #pragma unroll
            for (int mt = 0; mt < 2; ++mt)
                #pragma unroll
                for (int h = 0; h < 2; ++h) {
                    const int row = mbase + mt * 16 + h * 8 + q;
                    const float v = rmin[mt][h] + sssq[row];
                    atomicMin(&sdmin[row], __float_as_int(v));
                }
        }
        __syncthreads();

        // ---- phase 5: fold into global; reset own slot ----
        if (tid < S_) {
            const int v = sdmin[tid];
            atomicMin(reinterpret_cast<int*>(out_dist) + b * S_ + tid, v);
            sdmin[tid] = 0x7F800000;
        }
        // next phase-1 writes race-free: all phase-4 readers passed the sync
    }
}

// ---------------------------------------------------------------------------
// Kernel 2: fused MLP
// ---------------------------------------------------------------------------
__global__ void mlp_kernel(const float* __restrict__ dist,
                           const float* __restrict__ W1,
                           const float* __restrict__ b1,
                           const float* __restrict__ W2,
                           const float* __restrict__ b2,
                           float* __restrict__ out_cls)
{
    __shared__ float ds[S_];
    __shared__ float hs[H_];
    const int b = blockIdx.x;
    const int tid = threadIdx.x;   // 512

    if (tid < S_) ds[tid] = dist[b * S_ + tid];
    __syncthreads();

    {
        float acc = b1[tid];
        const float* w = W1 + tid * S_;
        #pragma unroll 8
        for (int s2 = 0; s2 < S_; ++s2) acc = fmaf(ds[s2], w[s2], acc);
        hs[tid] = fmaxf(acc, 0.f);
    }
    __syncthreads();

    const int warp = tid >> 5, lane = tid & 31;
    if (warp < C_) {
        const float* w = W2 + warp * H_;
        float acc = 0.f;
        #pragma unroll
        for (int j = lane; j < H_; j += 32) acc = fmaf(hs[j], w[j], acc);
        #pragma unroll
        for (int off = 16; off > 0; off >>= 1)
            acc += __shfl_down_sync(0xffffffffu, acc, off);
        if (lane == 0) out_cls[b * C_ + warp] = acc + b2[warp];
    }
}

// ---------------------------------------------------------------------------
extern "C" void kernel_launch(void* const* d_in, const int* in_sizes, int n_in,
                              void* d_out, int out_size)
{
    const float* x  = (const float*)d_in[0];
    const float* sh = (const float*)d_in[1];
    const float* W1 = (const float*)d_in[2];
    const float* b1 = (const float*)d_in[3];
    const float* W2 = (const float*)d_in[4];
    const float* b2 = (const float*)d_in[5];

    float* out_dist = (float*)d_out;
    float* out_cls  = (float*)d_out + B_ * S_;

    // init distances to a huge positive sentinel (0x7f7f7f7f ~ 3.39e38)
    cudaMemsetAsync(out_dist, 0x7f, B_ * S_ * sizeof(float), 0);

    dist_kernel<<<GRID, THR>>>(x, sh, out_dist);
    mlp_kernel<<<B_, H_>>>(out_dist, W1, b1, W2, b2, out_cls);
}

// round 7
// speedup vs baseline: 2.3211x; 1.7825x over previous
#include <cuda_runtime.h>
#include <cuda_fp16.h>
#include <cstdint>

// ---------------------------------------------------------------------------
// Problem constants
// ---------------------------------------------------------------------------
#define B_  32
#define D_  3
#define T_  16384
#define S_  128
#define L_  16
#define H_  512
#define C_  10
#define TP  16369          // T - L + 1 valid positions
#define SHN 48             // D*L = K (3 k-steps of 16)

#define NT      128        // positions per block tile (GEMM N-tile)
#define NTILES  (B_ * (T_ / NT))   // 4096
#define THR     256
#define GRID    296        // 2 blocks / SM
#define XT_W    (NT + L_)  // 144 elements per x row in tile

#define INF_F __int_as_float(0x7F800000)

// ---------------------------------------------------------------------------
// D(16x8) += A(16x16,row) * B(16x8,col)   f16 x f16 -> f32
__device__ __forceinline__ void mma16(float* d, uint32_t a0, uint32_t a1,
                                      uint32_t a2, uint32_t a3,
                                      uint32_t b0, uint32_t b1) {
    asm volatile(
        "mma.sync.aligned.m16n8k16.row.col.f32.f16.f16.f32 "
        "{%0,%1,%2,%3}, {%4,%5,%6,%7}, {%8,%9}, {%0,%1,%2,%3};"
        : "+f"(d[0]), "+f"(d[1]), "+f"(d[2]), "+f"(d[3])
        : "r"(a0), "r"(a1), "r"(a2), "r"(a3), "r"(b0), "r"(b1));
}

__device__ __forceinline__ uint32_t packh2(float lo, float hi) {
    __half2 h = __floats2half2_rn(lo, hi);
    return *reinterpret_cast<uint32_t*>(&h);
}

// ---------------------------------------------------------------------------
// Kernel 1: persistent fp16-MMA shapelet distance
// ---------------------------------------------------------------------------
__global__ __launch_bounds__(THR, 2) void dist_kernel(
    const float* __restrict__ x,
    const float* __restrict__ shg,
    float* __restrict__ out_dist)
{
    __shared__ float  xs[D_ * XT_W];        // raw fp32 (for exact wsq)
    __shared__ __half hA[D_ * XT_W];        // hA[i] = f16(x[i])   (even-pair copy)
    __shared__ __half hB[D_ * XT_W];        // hB[i] = f16(x[i+1]) (odd-pair copy)
    __shared__ float  swsq[NT];
    __shared__ float  sssq[S_];
    __shared__ int    sdmin[S_];

    const int tid  = threadIdx.x;
    const int wid  = tid >> 5;
    const int lane = tid & 31;
    const int q    = lane >> 2;      // groupID
    const int r    = lane & 3;       // threadID_in_group

    const int mbase = (wid & 3) * 32;       // warp's 32 M-rows
    const int nbase = (wid >> 2) * 64;      // warp's 64 N-cols

    // --- one-time: exact fp32 shapelet squared norms; A fragments -> regs ---
    if (tid < S_) {
        const float* srow = shg + tid * SHN;
        float ssq = 0.f;
        #pragma unroll
        for (int k = 0; k < SHN; ++k) ssq = fmaf(srow[k], srow[k], ssq);
        sssq[tid] = ssq;
        sdmin[tid] = 0x7F800000;
    }

    // A fragments: afr[ks][mt][4]; k = ks*16 + kk
    uint32_t afr[3][2][4];
    #pragma unroll
    for (int ks = 0; ks < 3; ++ks) {
        #pragma unroll
        for (int mt = 0; mt < 2; ++mt) {
            const int r0 = mbase + mt * 16 + q;       // row for a0/a2
            const int r1 = r0 + 8;                    // row for a1/a3
            const int k0 = ks * 16 + 2 * r;
            const float* p0 = shg + r0 * SHN + k0;
            const float* p1 = shg + r1 * SHN + k0;
            afr[ks][mt][0] = packh2(-2.f * p0[0], -2.f * p0[1]);
            afr[ks][mt][1] = packh2(-2.f * p1[0], -2.f * p1[1]);
            afr[ks][mt][2] = packh2(-2.f * p0[8], -2.f * p0[9]);
            afr[ks][mt][3] = packh2(-2.f * p1[8], -2.f * p1[9]);
        }
    }
    __syncthreads();

    const uint32_t* hA32 = reinterpret_cast<const uint32_t*>(hA);
    const uint32_t* hB32 = reinterpret_cast<const uint32_t*>(hB);
    const uint32_t* hw = (q & 1) ? hB32 : hA32;
    const int lane_off = q + 2 * r - (q & 1);

    for (int tile = blockIdx.x; tile < NTILES; tile += GRID) {
        const int b     = tile >> 7;                  // 128 tiles / batch
        const int tbase = (tile & 127) * NT;
        const float* xb = x + (size_t)b * D_ * T_;

        // ---- phase 1: load x tile (fp32 + two fp16 copies) ----
        {
            const int idx4 = tid;                     // 108 float4 total
            if (idx4 < (D_ * XT_W) / 4) {
                const int d = idx4 / (XT_W / 4);
                const int j = (idx4 % (XT_W / 4)) * 4;
                const int g = tbase + j;
                float4 v;
                if (g + 3 < T_) {
                    v = *reinterpret_cast<const float4*>(xb + d * T_ + g);
                } else {
                    v.x = (g     < T_) ? xb[d*T_ + g]     : 0.f;
                    v.y = (g + 1 < T_) ? xb[d*T_ + g + 1] : 0.f;
                    v.z = (g + 2 < T_) ? xb[d*T_ + g + 2] : 0.f;
                    v.w = (g + 3 < T_) ? xb[d*T_ + g + 3] : 0.f;
                }
                *reinterpret_cast<float4*>(&xs[d * XT_W + j]) = v;
                const int hi = d * XT_W + j;
                *reinterpret_cast<uint32_t*>(&hA[hi])     = packh2(v.x, v.y);
                *reinterpret_cast<uint32_t*>(&hA[hi + 2]) = packh2(v.z, v.w);
                if (j > 0) hB[hi - 1] = __float2half(v.x);
                hB[hi    ] = __float2half(v.y);
                hB[hi + 1] = __float2half(v.z);
                hB[hi + 2] = __float2half(v.w);
            }
        }
        __syncthreads();

        // ---- phase 2: wsq from raw fp32, poison invalid tail ----
        if (tid < NT) {
            float w0 = 0.f, w1 = 0.f, w2 = 0.f;
            #pragma unroll
            for (int l = 0; l < L_; ++l) {
                const float v0 = xs[0 * XT_W + tid + l];
                const float v1 = xs[1 * XT_W + tid + l];
                const float v2 = xs[2 * XT_W + tid + l];
                w0 = fmaf(v0, v0, w0);
                w1 = fmaf(v1, v1, w1);
                w2 = fmaf(v2, v2, w2);
            }
            swsq[tid] = (tbase + tid < TP) ? (w0 + w1 + w2) : INF_F;
        }

        // ---- phase 3: MMA, warp tile 32M x 64N, K=48 (3 k-steps) ----
        float acc[2][8][4];
        #pragma unroll
        for (int mt = 0; mt < 2; ++mt)
            #pragma unroll
            for (int nt = 0; nt < 8; ++nt)
                #pragma unroll
                for (int e = 0; e < 4; ++e) acc[mt][nt][e] = 0.f;

        #pragma unroll
        for (int ks = 0; ks < 3; ++ks) {
            const int base = (ks * XT_W + nbase + lane_off) >> 1;
            #pragma unroll
            for (int nt = 0; nt < 8; ++nt) {
                const uint32_t b0 = hw[base + nt * 4];
                const uint32_t b1 = hw[base + nt * 4 + 4];
                mma16(acc[0][nt], afr[ks][0][0], afr[ks][0][1],
                                  afr[ks][0][2], afr[ks][0][3], b0, b1);
                mma16(acc[1][nt], afr[ks][1][0], afr[ks][1][1],
                                  afr[ks][1][2], afr[ks][1][3], b0, b1);
            }
        }
        __syncthreads();   // swsq ready

        // ---- phase 4: dist = min_n(acc + wsq[n]); smem atomic min ----
        float wq[8][2];
        #pragma unroll
        for (int nt = 0; nt < 8; ++nt) {
            wq[nt][0] = swsq[nbase + nt * 8 + r * 2    ];
            wq[nt][1] = swsq[nbase + nt * 8 + r * 2 + 1];
        }
        float rmin[2][2];
        #pragma unroll
        for (int mt = 0; mt < 2; ++mt)
            #pragma unroll
            for (int h = 0; h < 2; ++h) {
                float m = INF_F;
                #pragma unroll
                for (int nt = 0; nt < 8; ++nt) {
                    m = fminf(m, acc[mt][nt][h * 2    ] + wq[nt][0]);
                    m = fminf(m, acc[mt][nt][h * 2 + 1] + wq[nt][1]);
                }
                rmin[mt][h] = m;
            }
        #pragma unroll
        for (int mt = 0; mt < 2; ++mt)
            #pragma unroll
            for (int h = 0; h < 2; ++h) {
                float v = rmin[mt][h];
                v = fminf(v, __shfl_xor_sync(0xffffffffu, v, 1));
                v = fminf(v, __shfl_xor_sync(0xffffffffu, v, 2));
                rmin[mt][h] = v;
            }
        if (r == 0) {
            #pragma unroll
            for (int mt = 0; mt < 2; ++mt)
                #pragma unroll
                for (int h = 0; h < 2; ++h) {
                    const int row = mbase + mt * 16 + h * 8 + q;
                    const float v = rmin[mt][h] + sssq[row];
                    atomicMin(&sdmin[row], __float_as_int(v));
                }
        }
        __syncthreads();

        // ---- phase 5: fold into global; reset own slot ----
        if (tid < S_) {
            const int v = sdmin[tid];
            atomicMin(reinterpret_cast<int*>(out_dist) + b * S_ + tid, v);
            sdmin[tid] = 0x7F800000;
        }
    }
}

// ---------------------------------------------------------------------------
// Kernel 2: fused MLP — coalesced (warp-cooperative dot products)
// ---------------------------------------------------------------------------
__global__ __launch_bounds__(512) void mlp_kernel(
    const float* __restrict__ dist,
    const float* __restrict__ W1,
    const float* __restrict__ b1,
    const float* __restrict__ W2,
    const float* __restrict__ b2,
    float* __restrict__ out_cls)
{
    __shared__ float4 ds4[S_ / 4];   // 128 floats
    __shared__ float  hs[H_];
    const int b    = blockIdx.x;
    const int tid  = threadIdx.x;    // 512 threads = 16 warps
    const int warp = tid >> 5;
    const int lane = tid & 31;

    if (tid < S_ / 4)
        ds4[tid] = reinterpret_cast<const float4*>(dist + b * S_)[tid];
    __syncthreads();

    // Layer 1: warp w computes neurons [w*32, w*32+32).
    // Lane holds ds[lane*4..lane*4+3]; per neuron one coalesced LDG.128.
    {
        const float4 d4 = ds4[lane];
        #pragma unroll
        for (int i = 0; i < 32; ++i) {
            const int h = warp * 32 + i;
            const float4 w4 =
                reinterpret_cast<const float4*>(W1 + h * S_)[lane];
            float acc = d4.x * w4.x;
            acc = fmaf(d4.y, w4.y, acc);
            acc = fmaf(d4.z, w4.z, acc);
            acc = fmaf(d4.w, w4.w, acc);
            #pragma unroll
            for (int off = 16; off > 0; off >>= 1)
                acc += __shfl_xor_sync(0xffffffffu, acc, off);
            if (lane == 0) hs[h] = fmaxf(acc + b1[h], 0.f);
        }
    }
    __syncthreads();

    // Layer 2: warp w (< 10) computes class w; lane covers 4 float4 chunks.
    if (warp < C_) {
        const float4* w4p = reinterpret_cast<const float4*>(W2 + warp * H_);
        const float4* h4p = reinterpret_cast<const float4*>(hs);
        float acc = 0.f;
        #pragma unroll
        for (int j = 0; j < H_ / (32 * 4); ++j) {       // 4 iterations
            const float4 w4 = w4p[lane + j * 32];
            const float4 h4 = h4p[lane + j * 32];
            acc = fmaf(w4.x, h4.x, acc);
            acc = fmaf(w4.y, h4.y, acc);
            acc = fmaf(w4.z, h4.z, acc);
            acc = fmaf(w4.w, h4.w, acc);
        }
        #pragma unroll
        for (int off = 16; off > 0; off >>= 1)
            acc += __shfl_xor_sync(0xffffffffu, acc, off);
        if (lane == 0) out_cls[b * C_ + warp] = acc + b2[warp];
    }
}

// ---------------------------------------------------------------------------
extern "C" void kernel_launch(void* const* d_in, const int* in_sizes, int n_in,
                              void* d_out, int out_size)
{
    const float* x  = (const float*)d_in[0];
    const float* sh = (const float*)d_in[1];
    const float* W1 = (const float*)d_in[2];
    const float* b1 = (const float*)d_in[3];
    const float* W2 = (const float*)d_in[4];
    const float* b2 = (const float*)d_in[5];

    float* out_dist = (float*)d_out;
    float* out_cls  = (float*)d_out + B_ * S_;

    // init distances to a huge positive sentinel (0x7f7f7f7f ~ 3.39e38)
    cudaMemsetAsync(out_dist, 0x7f, B_ * S_ * sizeof(float), 0);

    dist_kernel<<<GRID, THR>>>(x, sh, out_dist);
    mlp_kernel<<<B_, 512>>>(out_dist, W1, b1, W2, b2, out_cls);
}